// round 8
// baseline (speedup 1.0000x reference)
#include <cuda_runtime.h>
#include <cuda_bf16.h>
#include <cstdint>

// Problem dims (fixed)
#define M_DIM 1024
#define K_DIM 4096
#define N_DIM 4096
#define QBLK  32
#define NKB   (K_DIM / QBLK)      // 128

// GEMM tiling (fp8, 64x64 tiles, 4-stage pipeline, 3 CTAs/SM — R6 config)
#define BM 64
#define BN 64
#define BK 128                    // 128 fp8 = 128B rows (SW128), 4 quant blocks
#define STAGES 4
#define NITER (K_DIM / BK)        // 32
#define THREADS 128

// Stage smem: A(8K) | B(8K) | sx(1K) | sw(1K)
#define A_OFF   0
#define B_OFF   8192
#define SX_OFF  16384
#define SW_OFF  17408
#define STAGE_B 18432
#define SMEM_TOTAL (STAGES * STAGE_B)   // 73728

// Scratch (device globals)
__device__ uint8_t g_qx[(size_t)M_DIM * K_DIM];   // 4 MB  (e4m3 palette)
__device__ uint8_t g_qw[(size_t)N_DIM * K_DIM];   // 16 MB (e4m3 palette)
__device__ float   g_sx[(size_t)NKB * M_DIM];     // [kb][m] = bm/6
__device__ float   g_sw[(size_t)NKB * N_DIM];     // [kb][n] = bm/6

// ---------------------------------------------------------------------------
// PTX helpers
// ---------------------------------------------------------------------------
__device__ __forceinline__ uint32_t smem_u32(const void* p) {
    uint32_t a;
    asm("{ .reg .u64 t; cvta.to.shared.u64 t, %1; cvt.u32.u64 %0, t; }"
        : "=r"(a) : "l"(p));
    return a;
}
#define CP_ASYNC16(dst, src) \
    asm volatile("cp.async.cg.shared.global [%0], [%1], 16;" \
                 :: "r"(dst), "l"(src) : "memory")
#define CP_COMMIT() asm volatile("cp.async.commit_group;" ::: "memory")
#define CP_WAIT(n)  asm volatile("cp.async.wait_group %0;" :: "n"(n) : "memory")

#define LDSM4(r0, r1, r2, r3, addr) \
    asm volatile("ldmatrix.sync.aligned.m8n8.x4.shared.b16 {%0,%1,%2,%3}, [%4];" \
                 : "=r"(r0), "=r"(r1), "=r"(r2), "=r"(r3) : "r"(addr))

// fp8 e4m3 MMA, K=32, **fp16 accumulate**, C = 0.
// d0 = f16x2 {row qrow, cols (qcol, qcol+1)}, d1 = same cols, row qrow+8.
// Block partials are exact in f16 for this data (multiples of 0.25, |S|<512).
#define MMA_FP8_F16_Z(d0, d1, a, b0, b1) \
    asm volatile("mma.sync.aligned.m16n8k32.row.col.f16.e4m3.e4m3.f16 " \
        "{%0,%1},{%2,%3,%4,%5},{%6,%7},{%8,%8};" \
        : "=r"(d0), "=r"(d1) \
        : "r"((a)[0]), "r"((a)[1]), "r"((a)[2]), "r"((a)[3]), \
          "r"(b0), "r"(b1), "r"(0))

// f16x2 -> two f32
__device__ __forceinline__ void cvt2(uint32_t p, float& f0, float& f1) {
    asm("{ .reg .f16 lo, hi;\n\t"
        "  mov.b32 {lo, hi}, %2;\n\t"
        "  cvt.f32.f16 %0, lo;\n\t"
        "  cvt.f32.f16 %1, hi; }"
        : "=f"(f0), "=f"(f1) : "r"(p));
}

// packed f32x2 ops
__device__ __forceinline__ unsigned long long pk2(float lo, float hi) {
    unsigned long long d;
    asm("mov.b64 %0, {%1, %2};" : "=l"(d) : "f"(lo), "f"(hi));
    return d;
}
__device__ __forceinline__ unsigned long long pmul2(unsigned long long a,
                                                    unsigned long long b) {
    unsigned long long d;
    asm("mul.rn.f32x2 %0, %1, %2;" : "=l"(d) : "l"(a), "l"(b));
    return d;
}
__device__ __forceinline__ void pfma2(unsigned long long& acc,
                                      unsigned long long a,
                                      unsigned long long b) {
    asm("fma.rn.f32x2 %0, %1, %2, %0;" : "+l"(acc) : "l"(a), "l"(b));
}

__device__ __forceinline__ uint32_t swz128(uint32_t off) {
    return off ^ ((off >> 3) & 0x70);
}

// ---------------------------------------------------------------------------
// Quantize: 16 elems/thread, 2 threads per 32-elem block.
// EXACT argmin semantics (strict > ladder, ties to lower palette value);
// e4m3 byte emitted via byte_perm LUT (palette exact in e4m3).
// ---------------------------------------------------------------------------
__device__ __forceinline__ uint32_t pal_byte(float u, float r6) {
    float su = fabsf(u) * r6;
    uint32_t l = (su > 0.25f) + (su > 0.75f) + (su > 1.25f) + (su > 1.75f) +
                 (su > 2.5f)  + (su > 3.5f)  + (su > 5.0f);
    uint32_t b = __byte_perm(0x3C383000u, 0x4C484440u, l) & 0xffu;
    return b | ((__float_as_uint(u) >> 31) << 7);
}
__device__ __forceinline__ uint32_t pack4(const float4 v, float r6) {
    return  pal_byte(v.x, r6)        | (pal_byte(v.y, r6) << 8) |
           (pal_byte(v.z, r6) << 16) | (pal_byte(v.w, r6) << 24);
}

__global__ __launch_bounds__(256)
void quant_kernel(const float* __restrict__ t,
                  uint8_t* __restrict__ q,
                  float* __restrict__ s,
                  int rows) {
    const size_t gt = blockIdx.x * 256 + threadIdx.x;
    const size_t e0 = gt * 16;
    if (e0 >= (size_t)rows * K_DIM) return;

    float4 v[4];
    #pragma unroll
    for (int i = 0; i < 4; i++) v[i] = *(const float4*)(t + e0 + i * 4);

    float a = 0.0f;
    #pragma unroll
    for (int i = 0; i < 4; i++) {
        a = fmaxf(a, fmaxf(fmaxf(fabsf(v[i].x), fabsf(v[i].y)),
                           fmaxf(fabsf(v[i].z), fabsf(v[i].w))));
    }
    a = fmaxf(a, __shfl_xor_sync(0xffffffffu, a, 1));
    float bm = fmaxf(a, 1e-12f);
    float r6 = 6.0f / bm;

    uint4 pk;
    pk.x = pack4(v[0], r6);
    pk.y = pack4(v[1], r6);
    pk.z = pack4(v[2], r6);
    pk.w = pack4(v[3], r6);
    *(uint4*)(q + e0) = pk;

    if ((threadIdx.x & 1) == 0) {
        int row = (int)(e0 / K_DIM);
        int kb  = (int)((e0 % K_DIM) / QBLK);
        s[(size_t)kb * rows + row] = bm / 6.0f;
    }
}

// ---------------------------------------------------------------------------
// FP8 block-scaled GEMM, 64x64 CTA tile, 4 warps (2x2 of 32x32 warp tiles),
// 4-stage cp.async pipeline, 3 CTAs/SM, fp16-accum MMA + fp32 master accum.
// C[m,n] = sum_kb MMA_k32(qx,qw) * sx[m,kb]*sw[n,kb]
// ---------------------------------------------------------------------------
__global__ __launch_bounds__(THREADS, 3)
void gemm_fp8(const uint8_t* __restrict__ A,   // [M,K] e4m3
              const uint8_t* __restrict__ B,   // [N,K] e4m3
              const float* __restrict__ SX,    // [NKB][M]
              const float* __restrict__ SW,    // [NKB][N]
              float* __restrict__ C) {
    extern __shared__ __align__(1024) char smem[];
    const uint32_t sb = smem_u32(smem);
    const int tid  = threadIdx.x;
    const int wid  = tid >> 5;
    const int lane = tid & 31;
    const int m0   = (wid >> 1) * 32;
    const int n0   = (wid & 1) * 32;
    const int bm0  = blockIdx.y * BM;
    const int bn0  = blockIdx.x * BN;

    auto load_stage = [&](int buf, int it) {
        const uint32_t st = sb + buf * STAGE_B;
        const int k0 = it * BK;
        #pragma unroll
        for (int i = 0; i < 4; i++) {           // A: 64 rows x 8 chunks
            int c = tid + i * THREADS;
            int row = c >> 3, k16 = c & 7;
            const uint8_t* gA = A + (size_t)(bm0 + row) * K_DIM + k0 + k16 * 16;
            CP_ASYNC16(st + A_OFF + swz128(row * 128 + k16 * 16), gA);
        }
        #pragma unroll
        for (int i = 0; i < 4; i++) {           // B: 64 rows x 8 chunks
            int c = tid + i * THREADS;
            int row = c >> 3, k16 = c & 7;
            const uint8_t* gB = B + (size_t)(bn0 + row) * K_DIM + k0 + k16 * 16;
            CP_ASYNC16(st + B_OFF + swz128(row * 128 + k16 * 16), gB);
        }
        {   // scales
            int half = tid >> 6;                // 0 = sx, 1 = sw
            int cc   = tid & 63;
            int kbl  = cc >> 4;                 // 0..3
            int qq   = cc & 15;
            int kb   = it * 4 + kbl;
            if (half == 0) {
                const float* g = SX + (size_t)kb * M_DIM + bm0 + qq * 4;
                CP_ASYNC16(st + SX_OFF + kbl * 256 + qq * 16, g);
            } else {
                const float* g = SW + (size_t)kb * N_DIM + bn0 + qq * 4;
                CP_ASYNC16(st + SW_OFF + kbl * 256 + qq * 16, g);
            }
        }
    };

    // packed fp32 accumulators: acc2[tm][tn][h] = (c_even, c_odd)
    unsigned long long acc2[2][4][2];
    #pragma unroll
    for (int i = 0; i < 2; i++)
        #pragma unroll
        for (int j = 0; j < 4; j++) {
            acc2[i][j][0] = 0ull; acc2[i][j][1] = 0ull;
        }

    #pragma unroll
    for (int s = 0; s < STAGES - 1; s++) {
        load_stage(s, s);
        CP_COMMIT();
    }

    // ldmatrix lane addressing
    const int r       = lane & 7;
    const int sel     = lane >> 3;
    const int selRow  = (sel & 1) * 8;
    const int selByte = (sel >> 1) * 16;
    const int qrow    = lane >> 2;   // 0..7
    const int qcol    = (lane & 3) * 2;

    for (int it = 0; it < NITER; it++) {
        CP_WAIT(STAGES - 2);
        __syncthreads();

        if (it + STAGES - 1 < NITER)
            load_stage((it + STAGES - 1) & (STAGES - 1), it + STAGES - 1);
        CP_COMMIT();

        const int buf = it & (STAGES - 1);
        const uint32_t aB = sb + buf * STAGE_B + A_OFF;
        const uint32_t bB = sb + buf * STAGE_B + B_OFF;
        const char* sxS = smem + buf * STAGE_B + SX_OFF;
        const char* swS = smem + buf * STAGE_B + SW_OFF;

        #pragma unroll
        for (int kb = 0; kb < 4; kb++) {
            const int kbyte = kb * 32 + selByte;
            uint32_t a[2][4];
            #pragma unroll
            for (int tm = 0; tm < 2; tm++) {
                uint32_t addr = aB + swz128((m0 + tm * 16 + r + selRow) * 128 + kbyte);
                LDSM4(a[tm][0], a[tm][1], a[tm][2], a[tm][3], addr);
            }
            uint32_t b[2][4];
            #pragma unroll
            for (int g = 0; g < 2; g++) {
                uint32_t addr = bB + swz128((n0 + g * 16 + r + selRow) * 128 + kbyte);
                LDSM4(b[g][0], b[g][1], b[g][2], b[g][3], addr);
            }

            // fp16-accum MMAs: part[tm][tn][h] is an f16x2 pair (2 cols)
            uint32_t ph[2][4][2];
            #pragma unroll
            for (int tm = 0; tm < 2; tm++)
                #pragma unroll
                for (int g = 0; g < 2; g++) {
                    MMA_FP8_F16_Z(ph[tm][2*g][0],     ph[tm][2*g][1],
                                  a[tm], b[g][0], b[g][2]);
                    MMA_FP8_F16_Z(ph[tm][2*g + 1][0], ph[tm][2*g + 1][1],
                                  a[tm], b[g][1], b[g][3]);
                }

            // scales
            unsigned long long sxd[2][2];
            #pragma unroll
            for (int tm = 0; tm < 2; tm++)
                #pragma unroll
                for (int h = 0; h < 2; h++) {
                    float sx = *(const float*)(sxS + kb * 256 +
                                               (m0 + tm * 16 + qrow + 8 * h) * 4);
                    sxd[tm][h] = pk2(sx, sx);
                }
            unsigned long long swp[4];
            #pragma unroll
            for (int tn = 0; tn < 4; tn++)
                swp[tn] = *(const unsigned long long*)(swS + kb * 256 +
                                                       (n0 + tn * 8 + qcol) * 4);
            #pragma unroll
            for (int tm = 0; tm < 2; tm++)
                #pragma unroll
                for (int tn = 0; tn < 4; tn++) {
                    float f0, f1, f2, f3;
                    cvt2(ph[tm][tn][0], f0, f1);
                    cvt2(ph[tm][tn][1], f2, f3);
                    pfma2(acc2[tm][tn][0], pk2(f0, f1), pmul2(sxd[tm][0], swp[tn]));
                    pfma2(acc2[tm][tn][1], pk2(f2, f3), pmul2(sxd[tm][1], swp[tn]));
                }
        }
    }

    // epilogue: 8-byte packed stores
    #pragma unroll
    for (int tm = 0; tm < 2; tm++)
        #pragma unroll
        for (int h = 0; h < 2; h++) {
            int row = bm0 + m0 + tm * 16 + qrow + 8 * h;
            #pragma unroll
            for (int tn = 0; tn < 4; tn++) {
                unsigned long long v = acc2[tm][tn][h];
                *(unsigned long long*)(C + (size_t)row * N_DIM +
                                       bn0 + n0 + tn * 8 + qcol) = v;
            }
        }
}

// ---------------------------------------------------------------------------
extern "C" void kernel_launch(void* const* d_in, const int* in_sizes, int n_in,
                              void* d_out, int out_size) {
    (void)n_in; (void)in_sizes; (void)out_size;
    const float* x = (const float*)d_in[0];   // [M, K]
    const float* w = (const float*)d_in[1];   // [N, K]
    float* out = (float*)d_out;               // [M, N]

    uint8_t *qx = nullptr, *qw = nullptr;
    float *sx = nullptr, *sw = nullptr;
    cudaGetSymbolAddress((void**)&qx, g_qx);
    cudaGetSymbolAddress((void**)&qw, g_qw);
    cudaGetSymbolAddress((void**)&sx, g_sx);
    cudaGetSymbolAddress((void**)&sw, g_sw);

    quant_kernel<<<(M_DIM * (size_t)K_DIM) / 16 / 256, 256>>>(x, qx, sx, M_DIM);
    quant_kernel<<<(N_DIM * (size_t)K_DIM) / 16 / 256, 256>>>(w, qw, sw, N_DIM);

    cudaFuncSetAttribute(gemm_fp8,
                         cudaFuncAttributeMaxDynamicSharedMemorySize,
                         SMEM_TOTAL);
    dim3 grid(N_DIM / BN, M_DIM / BM);        // (64, 16) = 1024 CTAs
    gemm_fp8<<<grid, THREADS, SMEM_TOTAL>>>(qx, qw, sx, sw, out);
}

// round 9
// speedup vs baseline: 1.1034x; 1.1034x over previous
#include <cuda_runtime.h>
#include <cuda_bf16.h>
#include <cstdint>

// Problem dims (fixed)
#define M_DIM 1024
#define K_DIM 4096
#define N_DIM 4096
#define QBLK  32
#define NKB   (K_DIM / QBLK)      // 128

// GEMM tiling (fp8, 64x64 tiles, 4-stage pipeline, 3 CTAs/SM — R6 winner)
#define BM 64
#define BN 64
#define BK 128                    // 128 fp8 = 128B rows (SW128), 4 quant blocks
#define STAGES 4
#define NITER (K_DIM / BK)        // 32
#define THREADS 128

// Stage smem: A(8K) | B(8K) | sx(1K) | sw(1K)
#define A_OFF   0
#define B_OFF   8192
#define SX_OFF  16384
#define SW_OFF  17408
#define STAGE_B 18432
#define SMEM_TOTAL (STAGES * STAGE_B)   // 73728

// Scratch (device globals)
__device__ uint8_t g_qx[(size_t)M_DIM * K_DIM];   // 4 MB  (e4m3 palette)
__device__ uint8_t g_qw[(size_t)N_DIM * K_DIM];   // 16 MB (e4m3 palette)
__device__ float   g_sx[(size_t)NKB * M_DIM];     // [kb][m] = bm/6
__device__ float   g_sw[(size_t)NKB * N_DIM];     // [kb][n] = bm/6

// ---------------------------------------------------------------------------
// PTX helpers
// ---------------------------------------------------------------------------
__device__ __forceinline__ uint32_t smem_u32(const void* p) {
    uint32_t a;
    asm("{ .reg .u64 t; cvta.to.shared.u64 t, %1; cvt.u32.u64 %0, t; }"
        : "=r"(a) : "l"(p));
    return a;
}
#define CP_ASYNC16(dst, src) \
    asm volatile("cp.async.cg.shared.global [%0], [%1], 16;" \
                 :: "r"(dst), "l"(src) : "memory")
#define CP_COMMIT() asm volatile("cp.async.commit_group;" ::: "memory")
#define CP_WAIT(n)  asm volatile("cp.async.wait_group %0;" :: "n"(n) : "memory")

#define LDSM4(r0, r1, r2, r3, addr) \
    asm volatile("ldmatrix.sync.aligned.m8n8.x4.shared.b16 {%0,%1,%2,%3}, [%4];" \
                 : "=r"(r0), "=r"(r1), "=r"(r2), "=r"(r3) : "r"(addr))

// fp8 e4m3 MMA, K=32, fp32 accum, C = 0 (exact partial over one quant block)
#define MMA_FP8_Z(d, a, b0, b1) \
    asm volatile("mma.sync.aligned.m16n8k32.row.col.f32.e4m3.e4m3.f32 " \
        "{%0,%1,%2,%3},{%4,%5,%6,%7},{%8,%9},{%10,%10,%10,%10};" \
        : "=f"((d)[0]), "=f"((d)[1]), "=f"((d)[2]), "=f"((d)[3]) \
        : "r"((a)[0]), "r"((a)[1]), "r"((a)[2]), "r"((a)[3]), \
          "r"(b0), "r"(b1), "f"(0.0f))

// packed f32x2 ops
__device__ __forceinline__ unsigned long long pk2(float lo, float hi) {
    unsigned long long d;
    asm("mov.b64 %0, {%1, %2};" : "=l"(d) : "f"(lo), "f"(hi));
    return d;
}
__device__ __forceinline__ unsigned long long pmul2(unsigned long long a,
                                                    unsigned long long b) {
    unsigned long long d;
    asm("mul.rn.f32x2 %0, %1, %2;" : "=l"(d) : "l"(a), "l"(b));
    return d;
}
__device__ __forceinline__ void pfma2(unsigned long long& acc,
                                      unsigned long long a,
                                      unsigned long long b) {
    asm("fma.rn.f32x2 %0, %1, %2, %0;" : "+l"(acc) : "l"(a), "l"(b));
}

__device__ __forceinline__ uint32_t swz128(uint32_t off) {
    return off ^ ((off >> 3) & 0x70);
}

// ---------------------------------------------------------------------------
// Quantize v5: ceil-based EXACT snap (argmin tie-to-lower preserved):
//   su < 2 : p = ceil(2*su - 0.5) * 0.5     (ties 0.25/0.75/1.25/1.75 -> lower)
//   2..5   : p = min(ceil(su - 0.5), 4)     (ties 2.5/3.5/5 -> lower)
//   su > 5 : p = 6
// Then copysign + hardware e4m3x2 pack (palette values exact in e4m3).
// Fused: one grid quantizes x then w.
// ---------------------------------------------------------------------------
__device__ __forceinline__ float snap1(float v, float r6) {
    float su = fabsf(v) * r6;
    float pl = ceilf(fmaf(su, 2.0f, -0.5f)) * 0.5f;
    float ph = fminf(ceilf(su - 0.5f), 4.0f);
    float p  = su < 2.0f ? pl : ph;
    p = su > 5.0f ? 6.0f : p;
    return copysignf(p, v);
}
__device__ __forceinline__ uint32_t pack4_e4m3(float v0, float v1,
                                               float v2, float v3) {
    uint16_t lo, hi;
    asm("cvt.rn.satfinite.e4m3x2.f32 %0, %1, %2;" : "=h"(lo) : "f"(v1), "f"(v0));
    asm("cvt.rn.satfinite.e4m3x2.f32 %0, %1, %2;" : "=h"(hi) : "f"(v3), "f"(v2));
    return (uint32_t)lo | ((uint32_t)hi << 16);
}

#define XTHREADS ((M_DIM * (size_t)K_DIM) / 16)   // 262144 -> 1024 CTAs

__global__ __launch_bounds__(256)
void quant_fused_kernel(const float* __restrict__ x,
                        const float* __restrict__ w,
                        uint8_t* __restrict__ qx,
                        uint8_t* __restrict__ qw,
                        float* __restrict__ sx,
                        float* __restrict__ sw) {
    const size_t gt = blockIdx.x * 256 + threadIdx.x;

    const float* src;
    uint8_t* dst;
    float* sdst;
    int rows;
    size_t e0;
    if (gt < XTHREADS) {
        src = x;  dst = qx;  sdst = sx;  rows = M_DIM;  e0 = gt * 16;
    } else {
        src = w;  dst = qw;  sdst = sw;  rows = N_DIM;  e0 = (gt - XTHREADS) * 16;
    }

    float4 v[4];
    #pragma unroll
    for (int i = 0; i < 4; i++) v[i] = *(const float4*)(src + e0 + i * 4);

    float a = 0.0f;
    #pragma unroll
    for (int i = 0; i < 4; i++) {
        a = fmaxf(a, fmaxf(fmaxf(fabsf(v[i].x), fabsf(v[i].y)),
                           fmaxf(fabsf(v[i].z), fabsf(v[i].w))));
    }
    a = fmaxf(a, __shfl_xor_sync(0xffffffffu, a, 1));
    float bm = fmaxf(a, 1e-12f);
    float r6 = 6.0f / bm;

    uint4 pk;
    pk.x = pack4_e4m3(snap1(v[0].x, r6), snap1(v[0].y, r6),
                      snap1(v[0].z, r6), snap1(v[0].w, r6));
    pk.y = pack4_e4m3(snap1(v[1].x, r6), snap1(v[1].y, r6),
                      snap1(v[1].z, r6), snap1(v[1].w, r6));
    pk.z = pack4_e4m3(snap1(v[2].x, r6), snap1(v[2].y, r6),
                      snap1(v[2].z, r6), snap1(v[2].w, r6));
    pk.w = pack4_e4m3(snap1(v[3].x, r6), snap1(v[3].y, r6),
                      snap1(v[3].z, r6), snap1(v[3].w, r6));
    *(uint4*)(dst + e0) = pk;

    if ((threadIdx.x & 1) == 0) {
        int row = (int)(e0 / K_DIM);
        int kb  = (int)((e0 % K_DIM) / QBLK);
        sdst[(size_t)kb * rows + row] = bm / 6.0f;
    }
}

// ---------------------------------------------------------------------------
// FP8 block-scaled GEMM (R6 winner): 64x64 CTA tile, 4 warps (2x2 of 32x32),
// 4-stage cp.async pipeline, 3 CTAs/SM, fp32-accum fp8 MMA.
// C[m,n] = sum_kb MMA_k32(qx,qw) * sx[m,kb]*sw[n,kb]
// ---------------------------------------------------------------------------
__global__ __launch_bounds__(THREADS, 3)
void gemm_fp8(const uint8_t* __restrict__ A,   // [M,K] e4m3
              const uint8_t* __restrict__ B,   // [N,K] e4m3
              const float* __restrict__ SX,    // [NKB][M]
              const float* __restrict__ SW,    // [NKB][N]
              float* __restrict__ C) {
    extern __shared__ __align__(1024) char smem[];
    const uint32_t sb = smem_u32(smem);
    const int tid  = threadIdx.x;
    const int wid  = tid >> 5;
    const int lane = tid & 31;
    const int m0   = (wid >> 1) * 32;
    const int n0   = (wid & 1) * 32;
    const int bm0  = blockIdx.y * BM;
    const int bn0  = blockIdx.x * BN;

    auto load_stage = [&](int buf, int it) {
        const uint32_t st = sb + buf * STAGE_B;
        const int k0 = it * BK;
        #pragma unroll
        for (int i = 0; i < 4; i++) {           // A: 64 rows x 8 chunks
            int c = tid + i * THREADS;
            int row = c >> 3, k16 = c & 7;
            const uint8_t* gA = A + (size_t)(bm0 + row) * K_DIM + k0 + k16 * 16;
            CP_ASYNC16(st + A_OFF + swz128(row * 128 + k16 * 16), gA);
        }
        #pragma unroll
        for (int i = 0; i < 4; i++) {           // B: 64 rows x 8 chunks
            int c = tid + i * THREADS;
            int row = c >> 3, k16 = c & 7;
            const uint8_t* gB = B + (size_t)(bn0 + row) * K_DIM + k0 + k16 * 16;
            CP_ASYNC16(st + B_OFF + swz128(row * 128 + k16 * 16), gB);
        }
        {   // scales
            int half = tid >> 6;                // 0 = sx, 1 = sw
            int cc   = tid & 63;
            int kbl  = cc >> 4;                 // 0..3
            int qq   = cc & 15;
            int kb   = it * 4 + kbl;
            if (half == 0) {
                const float* g = SX + (size_t)kb * M_DIM + bm0 + qq * 4;
                CP_ASYNC16(st + SX_OFF + kbl * 256 + qq * 16, g);
            } else {
                const float* g = SW + (size_t)kb * N_DIM + bn0 + qq * 4;
                CP_ASYNC16(st + SW_OFF + kbl * 256 + qq * 16, g);
            }
        }
    };

    // packed fp32 accumulators: acc2[tm][tn][h] = (c_even, c_odd)
    unsigned long long acc2[2][4][2];
    #pragma unroll
    for (int i = 0; i < 2; i++)
        #pragma unroll
        for (int j = 0; j < 4; j++) {
            acc2[i][j][0] = 0ull; acc2[i][j][1] = 0ull;
        }

    #pragma unroll
    for (int s = 0; s < STAGES - 1; s++) {
        load_stage(s, s);
        CP_COMMIT();
    }

    // ldmatrix lane addressing
    const int r       = lane & 7;
    const int sel     = lane >> 3;
    const int selRow  = (sel & 1) * 8;
    const int selByte = (sel >> 1) * 16;
    const int qrow    = lane >> 2;   // 0..7
    const int qcol    = (lane & 3) * 2;

    for (int it = 0; it < NITER; it++) {
        CP_WAIT(STAGES - 2);
        __syncthreads();

        if (it + STAGES - 1 < NITER)
            load_stage((it + STAGES - 1) & (STAGES - 1), it + STAGES - 1);
        CP_COMMIT();

        const int buf = it & (STAGES - 1);
        const uint32_t aB = sb + buf * STAGE_B + A_OFF;
        const uint32_t bB = sb + buf * STAGE_B + B_OFF;
        const char* sxS = smem + buf * STAGE_B + SX_OFF;
        const char* swS = smem + buf * STAGE_B + SW_OFF;

        #pragma unroll
        for (int kb = 0; kb < 4; kb++) {
            const int kbyte = kb * 32 + selByte;
            uint32_t a[2][4];
            #pragma unroll
            for (int tm = 0; tm < 2; tm++) {
                uint32_t addr = aB + swz128((m0 + tm * 16 + r + selRow) * 128 + kbyte);
                LDSM4(a[tm][0], a[tm][1], a[tm][2], a[tm][3], addr);
            }
            uint32_t b[2][4];
            #pragma unroll
            for (int g = 0; g < 2; g++) {
                uint32_t addr = bB + swz128((n0 + g * 16 + r + selRow) * 128 + kbyte);
                LDSM4(b[g][0], b[g][1], b[g][2], b[g][3], addr);
            }

            float part[2][4][4];
            #pragma unroll
            for (int tm = 0; tm < 2; tm++)
                #pragma unroll
                for (int g = 0; g < 2; g++) {
                    MMA_FP8_Z(part[tm][2*g],     a[tm], b[g][0], b[g][2]);
                    MMA_FP8_Z(part[tm][2*g + 1], a[tm], b[g][1], b[g][3]);
                }

            // scales
            unsigned long long sxd[2][2];
            #pragma unroll
            for (int tm = 0; tm < 2; tm++)
                #pragma unroll
                for (int h = 0; h < 2; h++) {
                    float sx = *(const float*)(sxS + kb * 256 +
                                               (m0 + tm * 16 + qrow + 8 * h) * 4);
                    sxd[tm][h] = pk2(sx, sx);
                }
            unsigned long long swp[4];
            #pragma unroll
            for (int tn = 0; tn < 4; tn++)
                swp[tn] = *(const unsigned long long*)(swS + kb * 256 +
                                                       (n0 + tn * 8 + qcol) * 4);
            #pragma unroll
            for (int tm = 0; tm < 2; tm++)
                #pragma unroll
                for (int tn = 0; tn < 4; tn++) {
                    unsigned long long p01 = pk2(part[tm][tn][0], part[tm][tn][1]);
                    unsigned long long p23 = pk2(part[tm][tn][2], part[tm][tn][3]);
                    pfma2(acc2[tm][tn][0], p01, pmul2(sxd[tm][0], swp[tn]));
                    pfma2(acc2[tm][tn][1], p23, pmul2(sxd[tm][1], swp[tn]));
                }
        }
    }

    // epilogue: 8-byte packed stores
    #pragma unroll
    for (int tm = 0; tm < 2; tm++)
        #pragma unroll
        for (int h = 0; h < 2; h++) {
            int row = bm0 + m0 + tm * 16 + qrow + 8 * h;
            #pragma unroll
            for (int tn = 0; tn < 4; tn++) {
                unsigned long long v = acc2[tm][tn][h];
                *(unsigned long long*)(C + (size_t)row * N_DIM +
                                       bn0 + n0 + tn * 8 + qcol) = v;
            }
        }
}

// ---------------------------------------------------------------------------
extern "C" void kernel_launch(void* const* d_in, const int* in_sizes, int n_in,
                              void* d_out, int out_size) {
    (void)n_in; (void)in_sizes; (void)out_size;
    const float* x = (const float*)d_in[0];   // [M, K]
    const float* w = (const float*)d_in[1];   // [N, K]
    float* out = (float*)d_out;               // [M, N]

    uint8_t *qx = nullptr, *qw = nullptr;
    float *sx = nullptr, *sw = nullptr;
    cudaGetSymbolAddress((void**)&qx, g_qx);
    cudaGetSymbolAddress((void**)&qw, g_qw);
    cudaGetSymbolAddress((void**)&sx, g_sx);
    cudaGetSymbolAddress((void**)&sw, g_sw);

    // fused quant: x (1024 CTAs) + w (4096 CTAs) in one launch
    const int total_ctas = (int)(((M_DIM + N_DIM) * (size_t)K_DIM) / 16 / 256);
    quant_fused_kernel<<<total_ctas, 256>>>(x, w, qx, qw, sx, sw);

    cudaFuncSetAttribute(gemm_fp8,
                         cudaFuncAttributeMaxDynamicSharedMemorySize,
                         SMEM_TOTAL);
    dim3 grid(N_DIM / BN, M_DIM / BM);        // (64, 16) = 1024 CTAs
    gemm_fp8<<<grid, THREADS, SMEM_TOTAL>>>(qx, qw, sx, sw, out);
}